// round 7
// baseline (speedup 1.0000x reference)
#include <cuda_runtime.h>

// out[b,i,j,f] = x[b,i,f] * y[b,j,f]; second half of d_out = 0.75 * first half.
// Store-centric: one logical work item per float4 of the first output half,
// idx = (b*9 + ij)*32 + f4 -> store out[idx] is perfectly linear.
// Persistent grid (one resident wave, 148*8 CTAs) + batch-2 grid-stride loop:
// 4 loads front-batched, then 4 stores per loop body -> deeper per-warp
// outstanding-sector queue, no CTA churn.

__global__ __launch_bounds__(256)
void tp_kernel(const float4* __restrict__ x,
               const float4* __restrict__ y,
               float4* __restrict__ out,
               unsigned total, unsigned halfi)
{
    const unsigned stride = gridDim.x * blockDim.x;
    unsigned idx = blockIdx.x * blockDim.x + threadIdx.x;

    // batch-2 main loop
    for (; idx + stride < total; idx += 2 * stride) {
        unsigned i0 = idx, i1 = idx + stride;

        unsigned f40 = i0 & 31u, g0 = i0 >> 5;
        unsigned b0 = g0 / 9u, ij0 = g0 - b0 * 9u;
        unsigned ii0 = ij0 / 3u, jj0 = ij0 - ii0 * 3u;

        unsigned f41 = i1 & 31u, g1 = i1 >> 5;
        unsigned b1 = g1 / 9u, ij1 = g1 - b1 * 9u;
        unsigned ii1 = ij1 / 3u, jj1 = ij1 - ii1 * 3u;

        float4 xv0 = x[(b0 * 3u + ii0) * 32u + f40];
        float4 yv0 = y[(b0 * 3u + jj0) * 32u + f40];
        float4 xv1 = x[(b1 * 3u + ii1) * 32u + f41];
        float4 yv1 = y[(b1 * 3u + jj1) * 32u + f41];

        float4 p0, q0, p1, q1;
        p0.x = xv0.x * yv0.x; p0.y = xv0.y * yv0.y;
        p0.z = xv0.z * yv0.z; p0.w = xv0.w * yv0.w;
        p1.x = xv1.x * yv1.x; p1.y = xv1.y * yv1.y;
        p1.z = xv1.z * yv1.z; p1.w = xv1.w * yv1.w;
        q0.x = 0.75f * p0.x; q0.y = 0.75f * p0.y;
        q0.z = 0.75f * p0.z; q0.w = 0.75f * p0.w;
        q1.x = 0.75f * p1.x; q1.y = 0.75f * p1.y;
        q1.z = 0.75f * p1.z; q1.w = 0.75f * p1.w;

        out[i0] = p0;
        out[i1] = p1;
        out[halfi + i0] = q0;
        out[halfi + i1] = q1;
    }

    // tail
    if (idx < total) {
        unsigned f4 = idx & 31u, g = idx >> 5;
        unsigned b = g / 9u, ij = g - b * 9u;
        unsigned i = ij / 3u, j = ij - i * 3u;

        float4 xv = x[(b * 3u + i) * 32u + f4];
        float4 yv = y[(b * 3u + j) * 32u + f4];

        float4 p, q;
        p.x = xv.x * yv.x; p.y = xv.y * yv.y;
        p.z = xv.z * yv.z; p.w = xv.w * yv.w;
        q.x = 0.75f * p.x; q.y = 0.75f * p.y;
        q.z = 0.75f * p.z; q.w = 0.75f * p.w;

        out[idx] = p;
        out[halfi + idx] = q;
    }
}

extern "C" void kernel_launch(void* const* d_in, const int* in_sizes, int n_in,
                              void* d_out, int out_size)
{
    const float4* x = (const float4*)d_in[0];
    const float4* y = (const float4*)d_in[1];
    float4* out = (float4*)d_out;

    int B = in_sizes[0] / (3 * 128);          // 100000
    unsigned total = (unsigned)B * 9u * 32u;  // float4 elements in first half

    int threads = 256;
    int blocks = 148 * 8;                     // one persistent wave
    tp_kernel<<<blocks, threads>>>(x, y, out, total, total);
}

// round 8
// speedup vs baseline: 1.2035x; 1.2035x over previous
#include <cuda_runtime.h>

// out[b,i,j,f] = x[b,i,f] * y[b,j,f]; second half of d_out = 0.75 * first half.
// Store-centric: one thread per float4 of the first output half.
// idx = (b*9 + ij)*32 + f4 -> store out[idx] is perfectly linear.
// 2 loads + 2 stores per thread, ~22 regs -> max occupancy; HW work
// distributor pipelines CTA replacement (beats software persistent loop,
// measured R7). Stores are evict-first (__stcs): output lines are dead on
// arrival, keeping L2 capacity for input reuse/residency (loads stay cached:
// 3x reuse across threads + cross-replay residency observed in R6 traffic).

__global__ __launch_bounds__(256)
void tp_kernel(const float4* __restrict__ x,
               const float4* __restrict__ y,
               float4* __restrict__ out,
               unsigned total, unsigned halfi)
{
    unsigned idx = blockIdx.x * blockDim.x + threadIdx.x;
    if (idx >= total) return;

    unsigned f4 = idx & 31u;
    unsigned g  = idx >> 5;          // b*9 + ij
    unsigned b  = g / 9u;            // reciprocal-mul by compiler
    unsigned ij = g - b * 9u;
    unsigned i  = ij / 3u;
    unsigned j  = ij - i * 3u;

    float4 xv = x[(b * 3u + i) * 32u + f4];
    float4 yv = y[(b * 3u + j) * 32u + f4];

    float4 p;
    p.x = xv.x * yv.x;
    p.y = xv.y * yv.y;
    p.z = xv.z * yv.z;
    p.w = xv.w * yv.w;

    float4 q;
    q.x = 0.75f * p.x;
    q.y = 0.75f * p.y;
    q.z = 0.75f * p.z;
    q.w = 0.75f * p.w;

    __stcs(&out[idx], p);
    __stcs(&out[halfi + idx], q);
}

extern "C" void kernel_launch(void* const* d_in, const int* in_sizes, int n_in,
                              void* d_out, int out_size)
{
    const float4* x = (const float4*)d_in[0];
    const float4* y = (const float4*)d_in[1];
    float4* out = (float4*)d_out;

    int B = in_sizes[0] / (3 * 128);         // 100000
    unsigned total = (unsigned)B * 9u * 32u; // float4 elements in first half
    int threads = 256;
    int blocks = (int)((total + threads - 1) / threads);
    tp_kernel<<<blocks, threads>>>(x, y, out, total, total);
}